// round 5
// baseline (speedup 1.0000x reference)
#include <cuda_runtime.h>
#include <cstdint>

#define NB 8
#define NH 8
#define LQ 512
#define LK 512
#define NR 4
#define DD 64
#define NBH (NB*NH)
#define BM 32
#define SQP 36
#define SKP 132
#define SVP 68
#define SSP 516

typedef unsigned long long ull;

// Scratch for r-reduced K and V (16 MB total, static device globals per harness rules)
__device__ float g_ksum[NBH * LK * DD];
__device__ float g_vsum[NBH * LK * DD];

__device__ __forceinline__ ull pack2(float x) {
    ull r; unsigned int xi = __float_as_uint(x);
    asm("mov.b64 %0, {%1, %1};" : "=l"(r) : "r"(xi));
    return r;
}
__device__ __forceinline__ void ffma2(ull& c, ull a, ull b) {
    asm("fma.rn.f32x2 %0, %1, %2, %0;" : "+l"(c) : "l"(a), "l"(b));
}
__device__ __forceinline__ float2 unpack2(ull x) {
    float2 f;
    asm("mov.b64 {%0, %1}, %2;" : "=f"(f.x), "=f"(f.y) : "l"(x));
    return f;
}

// ---------------------------------------------------------------------------
// K1: ksum[bh][j][d] = sum_r k[bh][j][r][d];  vsum likewise.
// idx space = NBH*LK*DD = 2,097,152 ; grid 8192 x 256 exactly covers it.
// ---------------------------------------------------------------------------
__global__ void reduce_kv_kernel(const float* __restrict__ k,
                                 const float* __restrict__ v) {
    int idx = blockIdx.x * 256 + threadIdx.x;
    int d  = idx & 63;
    int j  = (idx >> 6) & 511;
    int bh = idx >> 15;
    size_t base = ((size_t)bh * LK + j) * (NR * DD) + d;
    const float* kp = k + base;
    const float* vp = v + base;
    g_ksum[idx] = (kp[0] + kp[DD]) + (kp[2*DD] + kp[3*DD]);
    g_vsum[idx] = (vp[0] + vp[DD]) + (vp[2*DD] + vp[3*DD]);
}

// ---------------------------------------------------------------------------
// K2: per CTA: one (bh), BM=32 query rows.
//   Phase A: S[32,512] = (Q/8)[32,64] @ KsumT[64,512]  (f32x2 packed FMA)
//            epilogue applies omega & mask (int32), stores into smem sS
//   Phase B: row-wise softmax (1 warp per row), writes attn to gmem + sS
//   Phase C: O[32,64] = P[32,512] @ Vsum[512,64]
// smem: sQt 64x36 | sK 64x132 (aliased by sV 64x68) | sS 32x516  = 106.5 KB
// ---------------------------------------------------------------------------
extern __shared__ float smem[];

__global__ __launch_bounds__(256, 2)
void attn_kernel(const float* __restrict__ q,
                 const float* __restrict__ omega,
                 const int* __restrict__ mask,
                 float* __restrict__ out_o,
                 float* __restrict__ out_attn) {
    float* sQt = smem;                  // [64][SQP]
    float* sK  = smem + 64 * SQP;       // [64][SKP]  (transposed ksum tile)
    float* sS  = sK + 64 * SKP;         // [32][SSP]

    const int tid   = threadIdx.x;
    const int bh    = blockIdx.y;
    const int b     = bh >> 3;
    const int qbase = blockIdx.x * BM;

    const float* ks = g_ksum + (size_t)bh * LK * DD;
    const float* vs = g_vsum + (size_t)bh * LK * DD;

    // Load Q block transposed, fold 1/TEMPERATURE
    for (int idx = tid; idx < DD * BM; idx += 256) {
        int d = idx & 63, m = idx >> 6;
        sQt[d * SQP + m] = q[((size_t)bh * LQ + qbase + m) * DD + d] * 0.125f;
    }

    const int tx = tid & 15, ty = tid >> 4;
    const int m0 = ty * 2, n0 = tx * 8;

    // ---------------- Phase A ----------------
    for (int c = 0; c < 4; ++c) {
        __syncthreads();
        // load KsumT tile for columns [c*128, c*128+128)
        for (int idx = tid; idx < DD * 128; idx += 256) {
            int d = idx & 63, jj = idx >> 6;
            sK[d * SKP + jj] = ks[(size_t)(c * 128 + jj) * DD + d];
        }
        __syncthreads();

        ull acc00 = 0, acc01 = 0, acc02 = 0, acc03 = 0;
        ull acc10 = 0, acc11 = 0, acc12 = 0, acc13 = 0;
        #pragma unroll 8
        for (int d = 0; d < DD; ++d) {
            float2 a = *(const float2*)(sQt + d * SQP + m0);
            ull a0 = pack2(a.x), a1 = pack2(a.y);
            const float* bpf = sK + d * SKP + n0;
            ulonglong2 bA = *(const ulonglong2*)(bpf);
            ulonglong2 bB = *(const ulonglong2*)(bpf + 4);
            ffma2(acc00, a0, bA.x); ffma2(acc01, a0, bA.y);
            ffma2(acc02, a0, bB.x); ffma2(acc03, a0, bB.y);
            ffma2(acc10, a1, bA.x); ffma2(acc11, a1, bA.y);
            ffma2(acc12, a1, bB.x); ffma2(acc13, a1, bB.y);
        }

        ull accs[2][4] = {{acc00, acc01, acc02, acc03},
                          {acc10, acc11, acc12, acc13}};
        #pragma unroll
        for (int i = 0; i < 2; ++i) {
            int gi = qbase + m0 + i;
            size_t rowoff = ((size_t)b * LQ + gi) * LK + c * 128 + n0;
            float4 o0 = *(const float4*)(omega + rowoff);
            float4 o1 = *(const float4*)(omega + rowoff + 4);
            int4 ma = *(const int4*)(mask + rowoff);
            int4 mc = *(const int4*)(mask + rowoff + 4);
            float2 v0 = unpack2(accs[i][0]), v1 = unpack2(accs[i][1]);
            float2 v2 = unpack2(accs[i][2]), v3 = unpack2(accs[i][3]);
            float r[8] = {v0.x * o0.x, v0.y * o0.y, v1.x * o0.z, v1.y * o0.w,
                          v2.x * o1.x, v2.y * o1.y, v3.x * o1.z, v3.y * o1.w};
            if (ma.x) r[0] = -1e9f;
            if (ma.y) r[1] = -1e9f;
            if (ma.z) r[2] = -1e9f;
            if (ma.w) r[3] = -1e9f;
            if (mc.x) r[4] = -1e9f;
            if (mc.y) r[5] = -1e9f;
            if (mc.z) r[6] = -1e9f;
            if (mc.w) r[7] = -1e9f;
            float* dst = sS + (m0 + i) * SSP + c * 128 + n0;
            *(float4*)dst       = make_float4(r[0], r[1], r[2], r[3]);
            *(float4*)(dst + 4) = make_float4(r[4], r[5], r[6], r[7]);
        }
    }

    __syncthreads();

    // ---------------- Phase B: softmax ----------------
    const int warp = tid >> 5, lane = tid & 31;
    #pragma unroll
    for (int rr = 0; rr < 4; ++rr) {
        int m = warp * 4 + rr;
        float* row = sS + m * SSP;
        float vals[16];
        float vmax = -3.4e38f;
        #pragma unroll
        for (int kk = 0; kk < 16; ++kk) {
            vals[kk] = row[kk * 32 + lane];
            vmax = fmaxf(vmax, vals[kk]);
        }
        #pragma unroll
        for (int o = 16; o > 0; o >>= 1)
            vmax = fmaxf(vmax, __shfl_xor_sync(0xffffffffu, vmax, o));
        float sum = 0.f;
        #pragma unroll
        for (int kk = 0; kk < 16; ++kk) {
            vals[kk] = __expf(vals[kk] - vmax);
            sum += vals[kk];
        }
        #pragma unroll
        for (int o = 16; o > 0; o >>= 1)
            sum += __shfl_xor_sync(0xffffffffu, sum, o);
        float inv = 1.0f / sum;
        size_t aoff = ((size_t)bh * LQ + qbase + m) * LK;
        #pragma unroll
        for (int kk = 0; kk < 16; ++kk) {
            float p = vals[kk] * inv;
            row[kk * 32 + lane] = p;
            out_attn[aoff + kk * 32 + lane] = p;
        }
    }

    // ---------------- Phase C: O = P @ Vsum ----------------
    float* sV = sK;  // alias
    const int d0 = tx * 4;
    ull oa0 = 0, oa1 = 0, ob0 = 0, ob1 = 0;
    for (int jt = 0; jt < 8; ++jt) {
        __syncthreads();
        for (int idx = tid; idx < 64 * DD; idx += 256) {
            int d = idx & 63, jj = idx >> 6;
            sV[jj * SVP + d] = vs[(size_t)(jt * 64 + jj) * DD + d];
        }
        __syncthreads();
        #pragma unroll 8
        for (int j = 0; j < 64; ++j) {
            float a0 = sS[m0 * SSP + jt * 64 + j];
            float a1 = sS[(m0 + 1) * SSP + jt * 64 + j];
            ull A0 = pack2(a0), A1 = pack2(a1);
            ulonglong2 bv = *(const ulonglong2*)(sV + j * SVP + d0);
            ffma2(oa0, A0, bv.x); ffma2(oa1, A0, bv.y);
            ffma2(ob0, A1, bv.x); ffma2(ob1, A1, bv.y);
        }
    }
    {
        float2 x0 = unpack2(oa0), x1 = unpack2(oa1);
        *(float4*)(out_o + ((size_t)bh * LQ + qbase + m0) * DD + d0) =
            make_float4(x0.x, x0.y, x1.x, x1.y);
        float2 y0 = unpack2(ob0), y1 = unpack2(ob1);
        *(float4*)(out_o + ((size_t)bh * LQ + qbase + m0 + 1) * DD + d0) =
            make_float4(y0.x, y0.y, y1.x, y1.y);
    }
}

// ---------------------------------------------------------------------------
extern "C" void kernel_launch(void* const* d_in, const int* in_sizes, int n_in,
                              void* d_out, int out_size) {
    const float* q     = (const float*)d_in[0];
    const float* k     = (const float*)d_in[1];
    const float* v     = (const float*)d_in[2];
    const float* omega = (const float*)d_in[3];
    const int*   mask  = (const int*)d_in[4];

    float* out_o    = (float*)d_out;
    float* out_attn = out_o + (size_t)NBH * LQ * DD;  // output first, then attn

    reduce_kv_kernel<<<8192, 256>>>(k, v);

    const int smem_bytes = (64 * SQP + 64 * SKP + BM * SSP) * (int)sizeof(float);
    cudaFuncSetAttribute(attn_kernel,
                         cudaFuncAttributeMaxDynamicSharedMemorySize,
                         smem_bytes);

    dim3 grid(LQ / BM, NBH);
    attn_kernel<<<grid, 256, smem_bytes>>>(q, omega, mask, out_o, out_attn);
}

// round 7
// speedup vs baseline: 1.8988x; 1.8988x over previous
#include <cuda_runtime.h>
#include <cstdint>

#define NBH 64
#define L   512
#define DD  64
#define SQP 68    // sQ row pad (floats)
#define SKP 260   // sKT row pad (floats), 1040B = 65*16 -> float4 aligned
#define SPP 68    // sP row pad
#define SVP 68    // sV row pad

typedef unsigned long long ull;

// Scratch (device globals; no allocation in kernel_launch)
__device__ float  g_ksumT[NBH * DD * L];   // [bh][d][j]  (transposed)
__device__ float  g_vsum [NBH * L * DD];   // [bh][j][d]  (natural)
__device__ float2 g_stats[NBH * L];        // per attn row: {M, 1/Z}

__device__ __forceinline__ ull pack2(float x) {
    ull r; unsigned int xi = __float_as_uint(x);
    asm("mov.b64 %0, {%1, %1};" : "=l"(r) : "r"(xi));
    return r;
}
__device__ __forceinline__ void ffma2(ull& c, ull a, ull b) {
    asm("fma.rn.f32x2 %0, %1, %2, %0;" : "+l"(c) : "l"(a), "l"(b));
}
__device__ __forceinline__ float2 unpack2(ull x) {
    float2 f;
    asm("mov.b64 {%0, %1}, %2;" : "=f"(f.x), "=f"(f.y) : "l"(x));
    return f;
}

// ---------------------------------------------------------------------------
// K1: reduce r; write ksum TRANSPOSED [bh][d][j] (via smem tile transpose)
//     and vsum natural [bh][j][d]. grid (8 jblocks, 64 bh) x 256 threads.
// ---------------------------------------------------------------------------
__global__ __launch_bounds__(256)
void reduce_kv_kernel(const float* __restrict__ k, const float* __restrict__ v) {
    __shared__ float sT[DD * 65];
    const int t  = threadIdx.x;
    const int jb = blockIdx.x;
    const int bh = blockIdx.y;

    #pragma unroll
    for (int p = 0; p < 4; ++p) {
        int f4 = p * 256 + t;
        int jl = f4 >> 4, dq = (f4 & 15) << 2;
        size_t base = (((size_t)bh * L + jb * 64 + jl) * 4) * DD + dq;
        float4 a0 = *(const float4*)(k + base);
        float4 a1 = *(const float4*)(k + base + DD);
        float4 a2 = *(const float4*)(k + base + 2 * DD);
        float4 a3 = *(const float4*)(k + base + 3 * DD);
        float ks0 = (a0.x + a1.x) + (a2.x + a3.x);
        float ks1 = (a0.y + a1.y) + (a2.y + a3.y);
        float ks2 = (a0.z + a1.z) + (a2.z + a3.z);
        float ks3 = (a0.w + a1.w) + (a2.w + a3.w);
        sT[(dq + 0) * 65 + jl] = ks0;
        sT[(dq + 1) * 65 + jl] = ks1;
        sT[(dq + 2) * 65 + jl] = ks2;
        sT[(dq + 3) * 65 + jl] = ks3;
        float4 b0 = *(const float4*)(v + base);
        float4 b1 = *(const float4*)(v + base + DD);
        float4 b2 = *(const float4*)(v + base + 2 * DD);
        float4 b3 = *(const float4*)(v + base + 3 * DD);
        float4 vs;
        vs.x = (b0.x + b1.x) + (b2.x + b3.x);
        vs.y = (b0.y + b1.y) + (b2.y + b3.y);
        vs.z = (b0.z + b1.z) + (b2.z + b3.z);
        vs.w = (b0.w + b1.w) + (b2.w + b3.w);
        *(float4*)(g_vsum + ((size_t)bh * L + jb * 64 + jl) * DD + dq) = vs;
    }
    __syncthreads();
    #pragma unroll
    for (int p = 0; p < 4; ++p) {
        int f4 = p * 256 + t;
        int dl = f4 >> 4, jq = (f4 & 15) << 2;
        float4 o;
        o.x = sT[dl * 65 + jq + 0];
        o.y = sT[dl * 65 + jq + 1];
        o.z = sT[dl * 65 + jq + 2];
        o.w = sT[dl * 65 + jq + 3];
        *(float4*)(g_ksumT + ((size_t)bh * DD + dl) * L + jb * 64 + jq) = o;
    }
}

// ---------------------------------------------------------------------------
// K2: S = (Q/8)@KsumT, apply omega/mask, write RAW S to attn region,
//     online per-row max/sum -> g_stats. No S in smem: warp owns 8 rows,
//     lane owns cols {4l..4l+3, 128+4l..128+4l+3} per 256-col chunk.
// grid (8, 64) x 256. smem = sQ[64][68] + sKT[64][260] = 84KB -> 2 CTA/SM.
// ---------------------------------------------------------------------------
extern __shared__ float smem[];

__global__ __launch_bounds__(256, 2)
void score_kernel(const float* __restrict__ q,
                  const float* __restrict__ omega,
                  const int*   __restrict__ mask,
                  float* __restrict__ sraw) {
    float* sQ  = smem;              // [64][SQP]
    float* sKT = smem + 64 * SQP;   // [64][SKP]

    const int t  = threadIdx.x;
    const int bh = blockIdx.y;
    const int b  = bh >> 3;
    const int qb = blockIdx.x * 64;
    const int w  = t >> 5, l = t & 31;

    // fill sQ (natural layout, fold 1/8)
    #pragma unroll
    for (int p = 0; p < 4; ++p) {
        int f4 = p * 256 + t;
        int r = f4 >> 4, dq = (f4 & 15) << 2;
        float4 qv = *(const float4*)(q + ((size_t)bh * L + qb + r) * DD + dq);
        qv.x *= 0.125f; qv.y *= 0.125f; qv.z *= 0.125f; qv.w *= 0.125f;
        *(float4*)(sQ + r * SQP + dq) = qv;
    }

    float M[8], Z[8];
    #pragma unroll
    for (int r = 0; r < 8; ++r) { M[r] = -3.4e38f; Z[r] = 0.f; }

    for (int c = 0; c < 2; ++c) {
        __syncthreads();
        // fill sKT chunk (dense copy from pre-transposed g_ksumT)
        #pragma unroll
        for (int p = 0; p < 16; ++p) {
            int f4 = p * 256 + t;
            int d = f4 >> 6, cq = (f4 & 63) << 2;
            float4 kv = *(const float4*)(g_ksumT + ((size_t)bh * DD + d) * L + c * 256 + cq);
            *(float4*)(sKT + d * SKP + cq) = kv;
        }
        __syncthreads();

        ull acc[8][4];
        #pragma unroll
        for (int r = 0; r < 8; ++r)
            #pragma unroll
            for (int i = 0; i < 4; ++i) acc[r][i] = 0;

        const float* bp = sKT + 4 * l;
        #pragma unroll 2
        for (int d = 0; d < DD; d += 2) {
            float2 a[8];
            #pragma unroll
            for (int r = 0; r < 8; ++r)
                a[r] = *(const float2*)(sQ + (8 * w + r) * SQP + d);
            #pragma unroll
            for (int dd = 0; dd < 2; ++dd) {
                ulonglong2 b0 = *(const ulonglong2*)(bp + (d + dd) * SKP);
                ulonglong2 b1 = *(const ulonglong2*)(bp + (d + dd) * SKP + 128);
                #pragma unroll
                for (int r = 0; r < 8; ++r) {
                    ull ar = pack2(dd ? a[r].y : a[r].x);
                    ffma2(acc[r][0], ar, b0.x);
                    ffma2(acc[r][1], ar, b0.y);
                    ffma2(acc[r][2], ar, b1.x);
                    ffma2(acc[r][3], ar, b1.y);
                }
            }
        }

        // epilogue: omega, mask, raw store, online softmax stats
        #pragma unroll
        for (int r = 0; r < 8; ++r) {
            int gi = qb + 8 * w + r;
            size_t orow = ((size_t)b * L + gi) * L + c * 256;
            float4 o0 = *(const float4*)(omega + orow + 4 * l);
            float4 o1 = *(const float4*)(omega + orow + 128 + 4 * l);
            int4 m0 = *(const int4*)(mask + orow + 4 * l);
            int4 m1 = *(const int4*)(mask + orow + 128 + 4 * l);
            float2 u0 = unpack2(acc[r][0]), u1 = unpack2(acc[r][1]);
            float2 u2 = unpack2(acc[r][2]), u3 = unpack2(acc[r][3]);
            float s0 = m0.x ? -1e9f : u0.x * o0.x;
            float s1 = m0.y ? -1e9f : u0.y * o0.y;
            float s2 = m0.z ? -1e9f : u1.x * o0.z;
            float s3 = m0.w ? -1e9f : u1.y * o0.w;
            float s4 = m1.x ? -1e9f : u2.x * o1.x;
            float s5 = m1.y ? -1e9f : u2.y * o1.y;
            float s6 = m1.z ? -1e9f : u3.x * o1.z;
            float s7 = m1.w ? -1e9f : u3.y * o1.w;

            size_t arow = ((size_t)bh * L + gi) * L + c * 256;
            *(float4*)(sraw + arow + 4 * l)       = make_float4(s0, s1, s2, s3);
            *(float4*)(sraw + arow + 128 + 4 * l) = make_float4(s4, s5, s6, s7);

            float cm = fmaxf(fmaxf(fmaxf(s0, s1), fmaxf(s2, s3)),
                             fmaxf(fmaxf(s4, s5), fmaxf(s6, s7)));
            #pragma unroll
            for (int o = 16; o > 0; o >>= 1)
                cm = fmaxf(cm, __shfl_xor_sync(0xffffffffu, cm, o));
            float nM = fmaxf(M[r], cm);
            float cs = __expf(s0 - nM) + __expf(s1 - nM) + __expf(s2 - nM) + __expf(s3 - nM)
                     + __expf(s4 - nM) + __expf(s5 - nM) + __expf(s6 - nM) + __expf(s7 - nM);
            #pragma unroll
            for (int o = 16; o > 0; o >>= 1)
                cs += __shfl_xor_sync(0xffffffffu, cs, o);
            Z[r] = Z[r] * __expf(M[r] - nM) + cs;
            M[r] = nM;
        }
    }
    if (l == 0) {
        #pragma unroll
        for (int r = 0; r < 8; ++r) {
            int gi = qb + 8 * w + r;
            g_stats[(size_t)bh * L + gi] = make_float2(M[r], 1.0f / Z[r]);
        }
    }
}

// ---------------------------------------------------------------------------
// K3: P = exp(S-M)/Z (written in place to attn) and O = P @ Vsum.
// grid 256 (4 tiles of 128 rows per bh) x 256. warp=16 rows, lane=2 d-cols.
// smem = sP[128][68] + sV[64][68] + sSt[256] = 53KB -> 2 CTA/SM.
// ---------------------------------------------------------------------------
__global__ __launch_bounds__(256, 2)
void out_kernel(float* __restrict__ attn, float* __restrict__ out_o) {
    float* sP  = smem;                    // [128][SPP]
    float* sV  = smem + 128 * SPP;        // [64][SVP]
    float* sSt = sV + 64 * SVP;           // 128 x {M, invZ}

    const int t  = threadIdx.x;
    const int bx = blockIdx.x;
    const int bh = bx >> 2;
    const int ib = (bx & 3) * 128;
    const int w  = t >> 5, l = t & 31;

    if (t < 128) {
        float2 st = g_stats[(size_t)bh * L + ib + t];
        sSt[2 * t] = st.x; sSt[2 * t + 1] = st.y;
    }

    ull acc[16];
    #pragma unroll
    for (int rr = 0; rr < 16; ++rr) acc[rr] = 0;

    for (int jc = 0; jc < 8; ++jc) {
        __syncthreads();
        // fill sV (dense copy)
        #pragma unroll
        for (int p = 0; p < 4; ++p) {
            int f4 = p * 256 + t;
            int j = f4 >> 4, dq = (f4 & 15) << 2;
            *(float4*)(sV + j * SVP + dq) =
                *(const float4*)(g_vsum + ((size_t)bh * L + jc * 64 + j) * DD + dq);
        }
        // fill sP: read raw S, exp, write final P back to gmem + smem
        #pragma unroll
        for (int p = 0; p < 8; ++p) {
            int f4 = p * 256 + t;
            int row = f4 >> 4, jq = (f4 & 15) << 2;
            size_t ga = ((size_t)bh * L + ib + row) * L + jc * 64 + jq;
            float4 rv = *(const float4*)(attn + ga);
            float mM = sSt[2 * row], iz = sSt[2 * row + 1];
            float4 pv;
            pv.x = __expf(rv.x - mM) * iz;
            pv.y = __expf(rv.y - mM) * iz;
            pv.z = __expf(rv.z - mM) * iz;
            pv.w = __expf(rv.w - mM) * iz;
            *(float4*)(attn + ga) = pv;
            *(float4*)(sP + row * SPP + jq) = pv;
        }
        __syncthreads();

        #pragma unroll 2
        for (int j = 0; j < 64; j += 2) {
            float2 a[16];
            #pragma unroll
            for (int rr = 0; rr < 16; ++rr)
                a[rr] = *(const float2*)(sP + (w * 16 + rr) * SPP + j);
            #pragma unroll
            for (int jj = 0; jj < 2; ++jj) {
                ull bb = *(const ull*)(sV + (j + jj) * SVP + 2 * l);
                #pragma unroll
                for (int rr = 0; rr < 16; ++rr)
                    ffma2(acc[rr], pack2(jj ? a[rr].y : a[rr].x), bb);
            }
        }
    }

    #pragma unroll
    for (int rr = 0; rr < 16; ++rr) {
        float2 ov = unpack2(acc[rr]);
        *(float2*)(out_o + ((size_t)bh * L + ib + w * 16 + rr) * DD + 2 * l) = ov;
    }
}

// ---------------------------------------------------------------------------
extern "C" void kernel_launch(void* const* d_in, const int* in_sizes, int n_in,
                              void* d_out, int out_size) {
    const float* q     = (const float*)d_in[0];
    const float* k     = (const float*)d_in[1];
    const float* v     = (const float*)d_in[2];
    const float* omega = (const float*)d_in[3];
    const int*   mask  = (const int*)d_in[4];

    float* out_o    = (float*)d_out;
    float* out_attn = out_o + (size_t)NBH * L * DD;   // [output | attn]

    const int smem2 = (64 * SQP + 64 * SKP) * (int)sizeof(float);        // 83968
    const int smem3 = (128 * SPP + 64 * SVP + 256) * (int)sizeof(float); // 53248
    cudaFuncSetAttribute(score_kernel, cudaFuncAttributeMaxDynamicSharedMemorySize, smem2);
    cudaFuncSetAttribute(out_kernel,   cudaFuncAttributeMaxDynamicSharedMemorySize, smem3);

    reduce_kv_kernel<<<dim3(8, NBH), 256>>>(k, v);
    score_kernel<<<dim3(8, NBH), 256, smem2>>>(q, omega, mask, out_attn);
    out_kernel<<<256, 256, smem3>>>(out_attn, out_o);
}

// round 8
// speedup vs baseline: 1.9081x; 1.0049x over previous
#include <cuda_runtime.h>
#include <cstdint>

#define NBH 64
#define L   512
#define DD  64
#define SQP 68    // sQ row pad (floats)
#define SKP 260   // sKT row pad (floats), 1040B = 65*16 -> float4 aligned
#define SPP 68    // sP row pad
#define SVP 68    // sV row pad

typedef unsigned long long ull;

// Scratch (device globals; no allocation in kernel_launch)
__device__ float  g_ksumT[NBH * DD * L];   // [bh][d][j]  (transposed)
__device__ float  g_vsum [NBH * L * DD];   // [bh][j][d]  (natural)
__device__ float2 g_stats[NBH * L];        // per attn row: {M, 1/Z}

__device__ __forceinline__ ull pack2(float x) {
    ull r; unsigned int xi = __float_as_uint(x);
    asm("mov.b64 %0, {%1, %1};" : "=l"(r) : "r"(xi));
    return r;
}
__device__ __forceinline__ void ffma2(ull& c, ull a, ull b) {
    asm("fma.rn.f32x2 %0, %1, %2, %0;" : "+l"(c) : "l"(a), "l"(b));
}
__device__ __forceinline__ float2 unpack2(ull x) {
    float2 f;
    asm("mov.b64 {%0, %1}, %2;" : "=f"(f.x), "=f"(f.y) : "l"(x));
    return f;
}

// ---------------------------------------------------------------------------
// K1: reduce r; write ksum TRANSPOSED [bh][d][j] (via smem tile transpose)
//     and vsum natural [bh][j][d]. grid (8 jblocks, 64 bh) x 256 threads.
// ---------------------------------------------------------------------------
__global__ __launch_bounds__(256)
void reduce_kv_kernel(const float* __restrict__ k, const float* __restrict__ v) {
    __shared__ float sT[DD * 65];
    const int t  = threadIdx.x;
    const int jb = blockIdx.x;
    const int bh = blockIdx.y;

    #pragma unroll
    for (int p = 0; p < 4; ++p) {
        int f4 = p * 256 + t;
        int jl = f4 >> 4, dq = (f4 & 15) << 2;
        size_t base = (((size_t)bh * L + jb * 64 + jl) * 4) * DD + dq;
        float4 a0 = *(const float4*)(k + base);
        float4 a1 = *(const float4*)(k + base + DD);
        float4 a2 = *(const float4*)(k + base + 2 * DD);
        float4 a3 = *(const float4*)(k + base + 3 * DD);
        float ks0 = (a0.x + a1.x) + (a2.x + a3.x);
        float ks1 = (a0.y + a1.y) + (a2.y + a3.y);
        float ks2 = (a0.z + a1.z) + (a2.z + a3.z);
        float ks3 = (a0.w + a1.w) + (a2.w + a3.w);
        sT[(dq + 0) * 65 + jl] = ks0;
        sT[(dq + 1) * 65 + jl] = ks1;
        sT[(dq + 2) * 65 + jl] = ks2;
        sT[(dq + 3) * 65 + jl] = ks3;
        float4 b0 = *(const float4*)(v + base);
        float4 b1 = *(const float4*)(v + base + DD);
        float4 b2 = *(const float4*)(v + base + 2 * DD);
        float4 b3 = *(const float4*)(v + base + 3 * DD);
        float4 vs;
        vs.x = (b0.x + b1.x) + (b2.x + b3.x);
        vs.y = (b0.y + b1.y) + (b2.y + b3.y);
        vs.z = (b0.z + b1.z) + (b2.z + b3.z);
        vs.w = (b0.w + b1.w) + (b2.w + b3.w);
        *(float4*)(g_vsum + ((size_t)bh * L + jb * 64 + jl) * DD + dq) = vs;
    }
    __syncthreads();
    #pragma unroll
    for (int p = 0; p < 4; ++p) {
        int f4 = p * 256 + t;
        int dl = f4 >> 4, jq = (f4 & 15) << 2;
        float4 o;
        o.x = sT[dl * 65 + jq + 0];
        o.y = sT[dl * 65 + jq + 1];
        o.z = sT[dl * 65 + jq + 2];
        o.w = sT[dl * 65 + jq + 3];
        *(float4*)(g_ksumT + ((size_t)bh * DD + dl) * L + jb * 64 + jq) = o;
    }
}

// ---------------------------------------------------------------------------
// K2: S = (Q/8)@KsumT, apply omega/mask, write RAW S to attn region,
//     online per-row max/sum -> g_stats. No S in smem: warp owns 8 rows,
//     lane owns cols {4l..4l+3, 128+4l..128+4l+3} per 256-col chunk.
// grid (8, 64) x 256. smem = sQ[64][68] + sKT[64][260] = 84KB -> 2 CTA/SM.
// ---------------------------------------------------------------------------
extern __shared__ float smem[];

__global__ __launch_bounds__(256, 2)
void score_kernel(const float* __restrict__ q,
                  const float* __restrict__ omega,
                  const int*   __restrict__ mask,
                  float* __restrict__ sraw) {
    float* sQ  = smem;              // [64][SQP]
    float* sKT = smem + 64 * SQP;   // [64][SKP]

    const int t  = threadIdx.x;
    const int bh = blockIdx.y;
    const int b  = bh >> 3;
    const int qb = blockIdx.x * 64;
    const int w  = t >> 5, l = t & 31;

    // fill sQ (natural layout, fold 1/8)
    #pragma unroll
    for (int p = 0; p < 4; ++p) {
        int f4 = p * 256 + t;
        int r = f4 >> 4, dq = (f4 & 15) << 2;
        float4 qv = *(const float4*)(q + ((size_t)bh * L + qb + r) * DD + dq);
        qv.x *= 0.125f; qv.y *= 0.125f; qv.z *= 0.125f; qv.w *= 0.125f;
        *(float4*)(sQ + r * SQP + dq) = qv;
    }

    float M[8], Z[8];
    #pragma unroll
    for (int r = 0; r < 8; ++r) { M[r] = -3.4e38f; Z[r] = 0.f; }

    for (int c = 0; c < 2; ++c) {
        __syncthreads();
        // fill sKT chunk (dense copy from pre-transposed g_ksumT)
        #pragma unroll
        for (int p = 0; p < 16; ++p) {
            int f4 = p * 256 + t;
            int d = f4 >> 6, cq = (f4 & 63) << 2;
            float4 kv = *(const float4*)(g_ksumT + ((size_t)bh * DD + d) * L + c * 256 + cq);
            *(float4*)(sKT + d * SKP + cq) = kv;
        }
        __syncthreads();

        ull acc[8][4];
        #pragma unroll
        for (int r = 0; r < 8; ++r)
            #pragma unroll
            for (int i = 0; i < 4; ++i) acc[r][i] = 0;

        const float* bp = sKT + 4 * l;
        #pragma unroll 2
        for (int d = 0; d < DD; d += 2) {
            float2 a[8];
            #pragma unroll
            for (int r = 0; r < 8; ++r)
                a[r] = *(const float2*)(sQ + (8 * w + r) * SQP + d);
            #pragma unroll
            for (int dd = 0; dd < 2; ++dd) {
                ulonglong2 b0 = *(const ulonglong2*)(bp + (d + dd) * SKP);
                ulonglong2 b1 = *(const ulonglong2*)(bp + (d + dd) * SKP + 128);
                #pragma unroll
                for (int r = 0; r < 8; ++r) {
                    ull ar = pack2(dd ? a[r].y : a[r].x);
                    ffma2(acc[r][0], ar, b0.x);
                    ffma2(acc[r][1], ar, b0.y);
                    ffma2(acc[r][2], ar, b1.x);
                    ffma2(acc[r][3], ar, b1.y);
                }
            }
        }

        // epilogue: omega, mask, raw store, online softmax stats
        #pragma unroll
        for (int r = 0; r < 8; ++r) {
            int gi = qb + 8 * w + r;
            size_t orow = ((size_t)b * L + gi) * L + c * 256;
            float4 o0 = *(const float4*)(omega + orow + 4 * l);
            float4 o1 = *(const float4*)(omega + orow + 128 + 4 * l);
            int4 m0 = *(const int4*)(mask + orow + 4 * l);
            int4 m1 = *(const int4*)(mask + orow + 128 + 4 * l);
            float2 u0 = unpack2(acc[r][0]), u1 = unpack2(acc[r][1]);
            float2 u2 = unpack2(acc[r][2]), u3 = unpack2(acc[r][3]);
            float s0 = m0.x ? -1e9f : u0.x * o0.x;
            float s1 = m0.y ? -1e9f : u0.y * o0.y;
            float s2 = m0.z ? -1e9f : u1.x * o0.z;
            float s3 = m0.w ? -1e9f : u1.y * o0.w;
            float s4 = m1.x ? -1e9f : u2.x * o1.x;
            float s5 = m1.y ? -1e9f : u2.y * o1.y;
            float s6 = m1.z ? -1e9f : u3.x * o1.z;
            float s7 = m1.w ? -1e9f : u3.y * o1.w;

            size_t arow = ((size_t)bh * L + gi) * L + c * 256;
            *(float4*)(sraw + arow + 4 * l)       = make_float4(s0, s1, s2, s3);
            *(float4*)(sraw + arow + 128 + 4 * l) = make_float4(s4, s5, s6, s7);

            float cm = fmaxf(fmaxf(fmaxf(s0, s1), fmaxf(s2, s3)),
                             fmaxf(fmaxf(s4, s5), fmaxf(s6, s7)));
            #pragma unroll
            for (int o = 16; o > 0; o >>= 1)
                cm = fmaxf(cm, __shfl_xor_sync(0xffffffffu, cm, o));
            float nM = fmaxf(M[r], cm);
            float cs = __expf(s0 - nM) + __expf(s1 - nM) + __expf(s2 - nM) + __expf(s3 - nM)
                     + __expf(s4 - nM) + __expf(s5 - nM) + __expf(s6 - nM) + __expf(s7 - nM);
            #pragma unroll
            for (int o = 16; o > 0; o >>= 1)
                cs += __shfl_xor_sync(0xffffffffu, cs, o);
            Z[r] = Z[r] * __expf(M[r] - nM) + cs;
            M[r] = nM;
        }
    }
    if (l == 0) {
        #pragma unroll
        for (int r = 0; r < 8; ++r) {
            int gi = qb + 8 * w + r;
            g_stats[(size_t)bh * L + gi] = make_float2(M[r], 1.0f / Z[r]);
        }
    }
}

// ---------------------------------------------------------------------------
// K3: P = exp(S-M)/Z (written in place to attn) and O = P @ Vsum.
// grid 256 (4 tiles of 128 rows per bh) x 256. warp=16 rows, lane=2 d-cols.
// smem = sP[128][68] + sV[64][68] + sSt[256] = 53KB -> 2 CTA/SM.
// ---------------------------------------------------------------------------
__global__ __launch_bounds__(256, 2)
void out_kernel(float* __restrict__ attn, float* __restrict__ out_o) {
    float* sP  = smem;                    // [128][SPP]
    float* sV  = smem + 128 * SPP;        // [64][SVP]
    float* sSt = sV + 64 * SVP;           // 128 x {M, invZ}

    const int t  = threadIdx.x;
    const int bx = blockIdx.x;
    const int bh = bx >> 2;
    const int ib = (bx & 3) * 128;
    const int w  = t >> 5, l = t & 31;

    if (t < 128) {
        float2 st = g_stats[(size_t)bh * L + ib + t];
        sSt[2 * t] = st.x; sSt[2 * t + 1] = st.y;
    }

    ull acc[16];
    #pragma unroll
    for (int rr = 0; rr < 16; ++rr) acc[rr] = 0;

    for (int jc = 0; jc < 8; ++jc) {
        __syncthreads();
        // fill sV (dense copy)
        #pragma unroll
        for (int p = 0; p < 4; ++p) {
            int f4 = p * 256 + t;
            int j = f4 >> 4, dq = (f4 & 15) << 2;
            *(float4*)(sV + j * SVP + dq) =
                *(const float4*)(g_vsum + ((size_t)bh * L + jc * 64 + j) * DD + dq);
        }
        // fill sP: read raw S, exp, write final P back to gmem + smem
        #pragma unroll
        for (int p = 0; p < 8; ++p) {
            int f4 = p * 256 + t;
            int row = f4 >> 4, jq = (f4 & 15) << 2;
            size_t ga = ((size_t)bh * L + ib + row) * L + jc * 64 + jq;
            float4 rv = *(const float4*)(attn + ga);
            float mM = sSt[2 * row], iz = sSt[2 * row + 1];
            float4 pv;
            pv.x = __expf(rv.x - mM) * iz;
            pv.y = __expf(rv.y - mM) * iz;
            pv.z = __expf(rv.z - mM) * iz;
            pv.w = __expf(rv.w - mM) * iz;
            *(float4*)(attn + ga) = pv;
            *(float4*)(sP + row * SPP + jq) = pv;
        }
        __syncthreads();

        #pragma unroll 2
        for (int j = 0; j < 64; j += 2) {
            float2 a[16];
            #pragma unroll
            for (int rr = 0; rr < 16; ++rr)
                a[rr] = *(const float2*)(sP + (w * 16 + rr) * SPP + j);
            #pragma unroll
            for (int jj = 0; jj < 2; ++jj) {
                ull bb = *(const ull*)(sV + (j + jj) * SVP + 2 * l);
                #pragma unroll
                for (int rr = 0; rr < 16; ++rr)
                    ffma2(acc[rr], pack2(jj ? a[rr].y : a[rr].x), bb);
            }
        }
    }

    #pragma unroll
    for (int rr = 0; rr < 16; ++rr) {
        float2 ov = unpack2(acc[rr]);
        *(float2*)(out_o + ((size_t)bh * L + ib + w * 16 + rr) * DD + 2 * l) = ov;
    }
}

// ---------------------------------------------------------------------------
extern "C" void kernel_launch(void* const* d_in, const int* in_sizes, int n_in,
                              void* d_out, int out_size) {
    const float* q     = (const float*)d_in[0];
    const float* k     = (const float*)d_in[1];
    const float* v     = (const float*)d_in[2];
    const float* omega = (const float*)d_in[3];
    const int*   mask  = (const int*)d_in[4];

    float* out_o    = (float*)d_out;
    float* out_attn = out_o + (size_t)NBH * L * DD;   // [output | attn]

    const int smem2 = (64 * SQP + 64 * SKP) * (int)sizeof(float);        // 83968
    const int smem3 = (128 * SPP + 64 * SVP + 256) * (int)sizeof(float); // 53248
    cudaFuncSetAttribute(score_kernel, cudaFuncAttributeMaxDynamicSharedMemorySize, smem2);
    cudaFuncSetAttribute(out_kernel,   cudaFuncAttributeMaxDynamicSharedMemorySize, smem3);

    reduce_kv_kernel<<<dim3(8, NBH), 256>>>(k, v);
    score_kernel<<<dim3(8, NBH), 256, smem2>>>(q, omega, mask, out_attn);
    out_kernel<<<256, 256, smem3>>>(out_attn, out_o);
}